// round 4
// baseline (speedup 1.0000x reference)
#include <cuda_runtime.h>
#include <cuda_bf16.h>

#define NN 100000
#define EE 1600000
#define HID 128
#define EPSV 1e-5f

typedef unsigned long long u64;

// Scratch (no cudaMalloc allowed).
__device__ float g_h[NN * HID];    // GEMM output h
__device__ float g_acc[NN * HID];  // aggregation accumulator
__device__ float g_cnt[NN];        // per-node degree (incl. self loop)

// ---------------------------------------------------------------------------
// f32x2 helpers (Blackwell packed dual-FP32)
// ---------------------------------------------------------------------------
__device__ __forceinline__ u64 pack2(float x, float y) {
    u64 r; asm("mov.b64 %0, {%1, %2};" : "=l"(r) : "f"(x), "f"(y)); return r;
}
__device__ __forceinline__ float2 unpack2(u64 p) {
    float2 f; asm("mov.b64 {%0, %1}, %2;" : "=f"(f.x), "=f"(f.y) : "l"(p)); return f;
}
__device__ __forceinline__ void fma2(u64& d, u64 a, u64 b) {
    asm("fma.rn.f32x2 %0, %1, %2, %0;" : "+l"(d) : "l"(a), "l"(b));
}

// ---------------------------------------------------------------------------
// degree kernels
// ---------------------------------------------------------------------------
__global__ void cnt_init_k(float* cnt) {
    int i = blockIdx.x * blockDim.x + threadIdx.x;
    if (i < NN) cnt[i] = 1.0f;  // self loop
}

__global__ void cnt_edge_k(const int* __restrict__ dst, float* cnt) {
    int e = blockIdx.x * blockDim.x + threadIdx.x;
    if (e < EE) atomicAdd(&cnt[dst[e]], 1.0f);
}

// ---------------------------------------------------------------------------
// GEMM: out[N x C] = f(X)[N x 128] @ W[128 x C] + bias
//   BNIN: f(x_row) = relu((x_row / cnt_row) * scale + shift)  (fused finalize)
//   DUAL: also write to out2 (self-loop accumulator init)
//   CLS:  instead of storing h, compute h @ Wc2 + bc2 -> out [N x 2]
// Thread tile: RPT rows x 8 cols, f32x2 packed FMA.
// ---------------------------------------------------------------------------
template <int C, bool RELU, bool DUAL, bool BNIN, bool CLS>
__global__ void __launch_bounds__(256) gemm_k(const float* __restrict__ X,
                                              const float* __restrict__ W,
                                              const float* __restrict__ bias,
                                              float* __restrict__ out,
                                              float* __restrict__ out2,
                                              const float* __restrict__ cnt,
                                              const float* __restrict__ g,
                                              const float* __restrict__ be,
                                              const float* __restrict__ m,
                                              const float* __restrict__ v,
                                              const float* __restrict__ Wc2,
                                              const float* __restrict__ bc2) {
    constexpr int CG2 = C / 8;        // 8-col groups per row: 16 (C=128) or 8 (C=64)
    constexpr int TRG = 256 / CG2;    // row groups: 16 or 32
    constexpr int RPT = 64 / TRG;     // rows per thread: 4 or 2
    constexpr int BM  = 64;

    __shared__ float xs[BM * 128];
    __shared__ float sc[128];
    __shared__ float sh[128];

    const int row0 = blockIdx.x * BM;
    const int nrow = min(BM, NN - row0);

    if (BNIN) {
        if (threadIdx.x < 128) {
            float s = rsqrtf(v[threadIdx.x] + EPSV) * g[threadIdx.x];
            sc[threadIdx.x] = s;
            sh[threadIdx.x] = be[threadIdx.x] - m[threadIdx.x] * s;
        }
        __syncthreads();
    }

    // coalesced float4 tile load (+ fused BN/ReLU for BNIN)
    {
        const float4* Xv = reinterpret_cast<const float4*>(X + (size_t)row0 * 128);
        float4* xsv = reinterpret_cast<float4*>(xs);
        for (int i = threadIdx.x; i < nrow * 32; i += 256) {
            float4 a = Xv[i];
            if (BNIN) {
                int r = i >> 5;
                int c = (i & 31) * 4;
                float ic = 1.0f / cnt[row0 + r];
                a.x = fmaxf(fmaf(a.x * ic, sc[c + 0], sh[c + 0]), 0.f);
                a.y = fmaxf(fmaf(a.y * ic, sc[c + 1], sh[c + 1]), 0.f);
                a.z = fmaxf(fmaf(a.z * ic, sc[c + 2], sh[c + 2]), 0.f);
                a.w = fmaxf(fmaf(a.w * ic, sc[c + 3], sh[c + 3]), 0.f);
            }
            xsv[i] = a;
        }
    }
    __syncthreads();

    const int tc2 = threadIdx.x % CG2;    // 8-col group
    const int tr  = threadIdx.x / CG2;    // row group

    u64 acc2[RPT][4];
#pragma unroll
    for (int r = 0; r < RPT; r++)
#pragma unroll
        for (int c = 0; c < 4; c++) acc2[r][c] = 0ULL;

    const float4* Wv = reinterpret_cast<const float4*>(W);
#pragma unroll 4
    for (int k = 0; k < 128; k++) {
        float4 w0 = __ldg(&Wv[k * (C / 4) + tc2 * 2]);
        float4 w1 = __ldg(&Wv[k * (C / 4) + tc2 * 2 + 1]);
        u64 wp0 = pack2(w0.x, w0.y);
        u64 wp1 = pack2(w0.z, w0.w);
        u64 wp2 = pack2(w1.x, w1.y);
        u64 wp3 = pack2(w1.z, w1.w);
#pragma unroll
        for (int r = 0; r < RPT; r++) {
            float xv = xs[(tr + r * TRG) * 128 + k];
            u64 xp = pack2(xv, xv);
            fma2(acc2[r][0], xp, wp0);
            fma2(acc2[r][1], xp, wp1);
            fma2(acc2[r][2], xp, wp2);
            fma2(acc2[r][3], xp, wp3);
        }
    }

    float4 b0 = reinterpret_cast<const float4*>(bias)[tc2 * 2];
    float4 b1 = reinterpret_cast<const float4*>(bias)[tc2 * 2 + 1];

#pragma unroll
    for (int r = 0; r < RPT; r++) {
        int row = row0 + tr + r * TRG;
        float2 a0 = unpack2(acc2[r][0]);
        float2 a1 = unpack2(acc2[r][1]);
        float2 a2 = unpack2(acc2[r][2]);
        float2 a3 = unpack2(acc2[r][3]);
        float h0 = a0.x + b0.x, h1 = a0.y + b0.y, h2 = a1.x + b0.z, h3 = a1.y + b0.w;
        float h4 = a2.x + b1.x, h5 = a2.y + b1.y, h6 = a3.x + b1.z, h7 = a3.y + b1.w;
        if (RELU) {
            h0 = fmaxf(h0, 0.f); h1 = fmaxf(h1, 0.f); h2 = fmaxf(h2, 0.f); h3 = fmaxf(h3, 0.f);
            h4 = fmaxf(h4, 0.f); h5 = fmaxf(h5, 0.f); h6 = fmaxf(h6, 0.f); h7 = fmaxf(h7, 0.f);
        }
        if (CLS) {
            // classifier tail: p_j = sum_c h_c * Wc2[c][j]; reduce over CG2 threads
            int c0 = tc2 * 8;
            float p0 = h0 * __ldg(&Wc2[(c0 + 0) * 2]) + h1 * __ldg(&Wc2[(c0 + 1) * 2])
                     + h2 * __ldg(&Wc2[(c0 + 2) * 2]) + h3 * __ldg(&Wc2[(c0 + 3) * 2])
                     + h4 * __ldg(&Wc2[(c0 + 4) * 2]) + h5 * __ldg(&Wc2[(c0 + 5) * 2])
                     + h6 * __ldg(&Wc2[(c0 + 6) * 2]) + h7 * __ldg(&Wc2[(c0 + 7) * 2]);
            float p1 = h0 * __ldg(&Wc2[(c0 + 0) * 2 + 1]) + h1 * __ldg(&Wc2[(c0 + 1) * 2 + 1])
                     + h2 * __ldg(&Wc2[(c0 + 2) * 2 + 1]) + h3 * __ldg(&Wc2[(c0 + 3) * 2 + 1])
                     + h4 * __ldg(&Wc2[(c0 + 4) * 2 + 1]) + h5 * __ldg(&Wc2[(c0 + 5) * 2 + 1])
                     + h6 * __ldg(&Wc2[(c0 + 6) * 2 + 1]) + h7 * __ldg(&Wc2[(c0 + 7) * 2 + 1]);
#pragma unroll
            for (int o = CG2 / 2; o; o >>= 1) {
                p0 += __shfl_xor_sync(0xffffffffu, p0, o);
                p1 += __shfl_xor_sync(0xffffffffu, p1, o);
            }
            if (tc2 == 0 && row < NN) {
                out[(size_t)row * 2 + 0] = p0 + bc2[0];
                out[(size_t)row * 2 + 1] = p1 + bc2[1];
            }
        } else if (row < NN) {
            float4 o0 = {h0, h1, h2, h3};
            float4 o1 = {h4, h5, h6, h7};
            reinterpret_cast<float4*>(out + (size_t)row * C)[tc2 * 2]     = o0;
            reinterpret_cast<float4*>(out + (size_t)row * C)[tc2 * 2 + 1] = o1;
            if (DUAL) {
                reinterpret_cast<float4*>(out2 + (size_t)row * C)[tc2 * 2]     = o0;
                reinterpret_cast<float4*>(out2 + (size_t)row * C)[tc2 * 2 + 1] = o1;
            }
        }
    }
}

// ---------------------------------------------------------------------------
// scatter: grid-stride, warp per edge, 4-deep pipelined gathers + v4 RED
// ---------------------------------------------------------------------------
#define SC_BLOCKS 1184  /* 8 blocks/SM on 148 SMs */

__device__ __forceinline__ void red_add_v4(float* addr, float4 v) {
    asm volatile("red.global.add.v4.f32 [%0], {%1, %2, %3, %4};"
                 :: "l"(addr), "f"(v.x), "f"(v.y), "f"(v.z), "f"(v.w)
                 : "memory");
}

__global__ void __launch_bounds__(256) scatter_k(const int* __restrict__ src,
                                                 const int* __restrict__ dst,
                                                 const float* __restrict__ h,
                                                 float* __restrict__ acc) {
    const int warp = (blockIdx.x * 256 + threadIdx.x) >> 5;
    const int lane = threadIdx.x & 31;
    const int nw = SC_BLOCKS * 8;

    int e = warp;
    for (; e + 3 * nw < EE; e += 4 * nw) {
        int s0 = __ldg(&src[e]),          d0 = __ldg(&dst[e]);
        int s1 = __ldg(&src[e + nw]),     d1 = __ldg(&dst[e + nw]);
        int s2 = __ldg(&src[e + 2 * nw]), d2 = __ldg(&dst[e + 2 * nw]);
        int s3 = __ldg(&src[e + 3 * nw]), d3 = __ldg(&dst[e + 3 * nw]);
        float4 v0 = __ldg(&reinterpret_cast<const float4*>(h + (size_t)s0 * HID)[lane]);
        float4 v1 = __ldg(&reinterpret_cast<const float4*>(h + (size_t)s1 * HID)[lane]);
        float4 v2 = __ldg(&reinterpret_cast<const float4*>(h + (size_t)s2 * HID)[lane]);
        float4 v3 = __ldg(&reinterpret_cast<const float4*>(h + (size_t)s3 * HID)[lane]);
        red_add_v4(acc + (size_t)d0 * HID + lane * 4, v0);
        red_add_v4(acc + (size_t)d1 * HID + lane * 4, v1);
        red_add_v4(acc + (size_t)d2 * HID + lane * 4, v2);
        red_add_v4(acc + (size_t)d3 * HID + lane * 4, v3);
    }
    for (; e < EE; e += nw) {
        int s0 = __ldg(&src[e]), d0 = __ldg(&dst[e]);
        float4 v0 = __ldg(&reinterpret_cast<const float4*>(h + (size_t)s0 * HID)[lane]);
        red_add_v4(acc + (size_t)d0 * HID + lane * 4, v0);
    }
}

// ---------------------------------------------------------------------------
// launch
// ---------------------------------------------------------------------------
extern "C" void kernel_launch(void* const* d_in, const int* in_sizes, int n_in,
                              void* d_out, int out_size) {
    const float* x   = (const float*)d_in[0];
    const int*   ei  = (const int*)d_in[1];   // int32 edge indices
    const float *W1 = (const float*)d_in[2],  *b1  = (const float*)d_in[3];
    const float *g1 = (const float*)d_in[4],  *be1 = (const float*)d_in[5];
    const float *m1 = (const float*)d_in[6],  *v1  = (const float*)d_in[7];
    const float *W2 = (const float*)d_in[8],  *b2  = (const float*)d_in[9];
    const float *g2 = (const float*)d_in[10], *be2 = (const float*)d_in[11];
    const float *m2 = (const float*)d_in[12], *v2  = (const float*)d_in[13];
    const float *Wc1 = (const float*)d_in[14], *bc1 = (const float*)d_in[15];
    const float *Wc2 = (const float*)d_in[16], *bc2 = (const float*)d_in[17];
    float* out = (float*)d_out;

    const int* src = ei;
    const int* dst = ei + EE;

    float *hb, *ab, *cb;
    cudaGetSymbolAddress((void**)&hb, g_h);
    cudaGetSymbolAddress((void**)&ab, g_acc);
    cudaGetSymbolAddress((void**)&cb, g_cnt);

    const int GB = (NN + 63) / 64;

    // degrees (self loop = 1)
    cnt_init_k<<<(NN + 255) / 256, 256>>>(cb);
    cnt_edge_k<<<(EE + 255) / 256, 256>>>(dst, cb);

    // layer 1: h = x@W1+b1 -> h, acc
    gemm_k<128, false, true, false, false><<<GB, 256>>>(x, W1, b1, hb, ab,
        nullptr, nullptr, nullptr, nullptr, nullptr, nullptr, nullptr);
    scatter_k<<<SC_BLOCKS, 256>>>(src, dst, hb, ab);

    // layer 2: fused finalize(l1) -> GEMM -> h, acc (block-disjoint in-place on acc)
    gemm_k<128, false, true, true, false><<<GB, 256>>>(ab, W2, b2, hb, ab,
        cb, g1, be1, m1, v1, nullptr, nullptr);
    scatter_k<<<SC_BLOCKS, 256>>>(src, dst, hb, ab);

    // classifier: fused finalize(l2) -> GEMM(relu) -> @Wc2 + bc2 -> out [N x 2]
    gemm_k<64, true, false, true, true><<<GB, 256>>>(ab, Wc1, bc1, out, nullptr,
        cb, g2, be2, m2, v2, Wc2, bc2);
}

// round 5
// speedup vs baseline: 1.2907x; 1.2907x over previous
#include <cuda_runtime.h>
#include <cuda_bf16.h>

#define NN 100000
#define EE 1600000
#define HID 128
#define EPSV 1e-5f

// Scratch (no cudaMalloc allowed).
__device__ float g_h[NN * HID];    // GEMM output h
__device__ float g_acc[NN * HID];  // aggregation accumulator
__device__ float g_cnt[NN];        // per-node degree (incl. self loop)

// ---------------------------------------------------------------------------
// degree kernels
// ---------------------------------------------------------------------------
__global__ void cnt_init_k(float* cnt) {
    int i = blockIdx.x * blockDim.x + threadIdx.x;
    if (i < NN) cnt[i] = 1.0f;  // self loop
}

__global__ void cnt_edge_k(const int* __restrict__ dst, float* cnt) {
    int e = blockIdx.x * blockDim.x + threadIdx.x;
    if (e < EE) atomicAdd(&cnt[dst[e]], 1.0f);
}

// ---------------------------------------------------------------------------
// GEMM: out[N x C] = f(X)[N x 128] @ W[128 x C] + bias   (scalar FFMA, R3-proven)
//   BNIN: f(x_row) = relu((x_row / cnt_row) * scale + shift)  (fused finalize)
//   DUAL: also write to out2 (self-loop accumulator init)
//   CLS:  don't store h; compute h @ Wc2 + bc2 -> out [N x 2]
// ---------------------------------------------------------------------------
template <int C, bool RELU, bool DUAL, bool BNIN, bool CLS>
__global__ void __launch_bounds__(256) gemm_k(const float* __restrict__ X,
                                              const float* __restrict__ W,
                                              const float* __restrict__ bias,
                                              float* __restrict__ out,
                                              float* __restrict__ out2,
                                              const float* __restrict__ cnt,
                                              const float* __restrict__ g,
                                              const float* __restrict__ be,
                                              const float* __restrict__ m,
                                              const float* __restrict__ v,
                                              const float* __restrict__ Wc2,
                                              const float* __restrict__ bc2) {
    constexpr int CG  = C / 4;          // float4 col groups (32 or 16)
    constexpr int RT  = 256 / CG;       // row-thread groups (8 or 16)
    constexpr int RPT = (C == 128) ? 8 : 4;
    constexpr int BM  = RT * RPT;       // 64 rows per block

    __shared__ float xs[BM * 128];
    __shared__ float sc[128];
    __shared__ float sh[128];

    const int row0 = blockIdx.x * BM;
    const int nrow = min(BM, NN - row0);

    if (BNIN) {
        if (threadIdx.x < 128) {
            float s = rsqrtf(v[threadIdx.x] + EPSV) * g[threadIdx.x];
            sc[threadIdx.x] = s;
            sh[threadIdx.x] = be[threadIdx.x] - m[threadIdx.x] * s;
        }
        __syncthreads();
    }

    // coalesced float4 tile load (+ fused BN/ReLU for BNIN)
    {
        const float4* Xv = reinterpret_cast<const float4*>(X + (size_t)row0 * 128);
        float4* xsv = reinterpret_cast<float4*>(xs);
        for (int i = threadIdx.x; i < nrow * 32; i += 256) {
            float4 a = Xv[i];
            if (BNIN) {
                int r = i >> 5;
                int c = (i & 31) * 4;
                float ic = 1.0f / cnt[row0 + r];
                a.x = fmaxf(fmaf(a.x * ic, sc[c + 0], sh[c + 0]), 0.f);
                a.y = fmaxf(fmaf(a.y * ic, sc[c + 1], sh[c + 1]), 0.f);
                a.z = fmaxf(fmaf(a.z * ic, sc[c + 2], sh[c + 2]), 0.f);
                a.w = fmaxf(fmaf(a.w * ic, sc[c + 3], sh[c + 3]), 0.f);
            }
            xsv[i] = a;
        }
    }
    __syncthreads();

    const int tc = threadIdx.x % CG;    // column group (4 cols)
    const int tr = threadIdx.x / CG;    // row group

    float acc[RPT][4];
#pragma unroll
    for (int r = 0; r < RPT; r++) {
        acc[r][0] = 0.f; acc[r][1] = 0.f; acc[r][2] = 0.f; acc[r][3] = 0.f;
    }

    const float4* Wv = reinterpret_cast<const float4*>(W);
#pragma unroll 4
    for (int k = 0; k < 128; k++) {
        float4 w = __ldg(&Wv[k * CG + tc]);
#pragma unroll
        for (int r = 0; r < RPT; r++) {
            float xv = xs[(tr + r * RT) * 128 + k];
            acc[r][0] = fmaf(xv, w.x, acc[r][0]);
            acc[r][1] = fmaf(xv, w.y, acc[r][1]);
            acc[r][2] = fmaf(xv, w.z, acc[r][2]);
            acc[r][3] = fmaf(xv, w.w, acc[r][3]);
        }
    }

    float4 bv = reinterpret_cast<const float4*>(bias)[tc];
#pragma unroll
    for (int r = 0; r < RPT; r++) {
        int row = row0 + tr + r * RT;
        float h0 = acc[r][0] + bv.x;
        float h1 = acc[r][1] + bv.y;
        float h2 = acc[r][2] + bv.z;
        float h3 = acc[r][3] + bv.w;
        if (RELU) {
            h0 = fmaxf(h0, 0.f); h1 = fmaxf(h1, 0.f);
            h2 = fmaxf(h2, 0.f); h3 = fmaxf(h3, 0.f);
        }
        if (CLS) {
            // p_j = sum_c h_c * Wc2[c][j], c spread over CG threads x 4 cols
            int c0 = tc * 4;
            float p0 = h0 * __ldg(&Wc2[(c0 + 0) * 2])     + h1 * __ldg(&Wc2[(c0 + 1) * 2])
                     + h2 * __ldg(&Wc2[(c0 + 2) * 2])     + h3 * __ldg(&Wc2[(c0 + 3) * 2]);
            float p1 = h0 * __ldg(&Wc2[(c0 + 0) * 2 + 1]) + h1 * __ldg(&Wc2[(c0 + 1) * 2 + 1])
                     + h2 * __ldg(&Wc2[(c0 + 2) * 2 + 1]) + h3 * __ldg(&Wc2[(c0 + 3) * 2 + 1]);
#pragma unroll
            for (int o = CG / 2; o; o >>= 1) {
                p0 += __shfl_xor_sync(0xffffffffu, p0, o);
                p1 += __shfl_xor_sync(0xffffffffu, p1, o);
            }
            if (tc == 0 && row < NN) {
                out[(size_t)row * 2 + 0] = p0 + bc2[0];
                out[(size_t)row * 2 + 1] = p1 + bc2[1];
            }
        } else if (row < NN) {
            float4 o = {h0, h1, h2, h3};
            reinterpret_cast<float4*>(out + (size_t)row * C)[tc] = o;
            if (DUAL)
                reinterpret_cast<float4*>(out2 + (size_t)row * C)[tc] = o;
        }
    }
}

// ---------------------------------------------------------------------------
// scatter: grid-stride, warp per edge, 4-deep pipelined gathers + v4 RED
// ---------------------------------------------------------------------------
#define SC_BLOCKS 1184  /* 8 blocks/SM on 148 SMs */

__device__ __forceinline__ void red_add_v4(float* addr, float4 v) {
    asm volatile("red.global.add.v4.f32 [%0], {%1, %2, %3, %4};"
                 :: "l"(addr), "f"(v.x), "f"(v.y), "f"(v.z), "f"(v.w)
                 : "memory");
}

__global__ void __launch_bounds__(256) scatter_k(const int* __restrict__ src,
                                                 const int* __restrict__ dst,
                                                 const float* __restrict__ h,
                                                 float* __restrict__ acc) {
    const int warp = (blockIdx.x * 256 + threadIdx.x) >> 5;
    const int lane = threadIdx.x & 31;
    const int nw = SC_BLOCKS * 8;

    int e = warp;
    for (; e + 3 * nw < EE; e += 4 * nw) {
        int s0 = __ldg(&src[e]),          d0 = __ldg(&dst[e]);
        int s1 = __ldg(&src[e + nw]),     d1 = __ldg(&dst[e + nw]);
        int s2 = __ldg(&src[e + 2 * nw]), d2 = __ldg(&dst[e + 2 * nw]);
        int s3 = __ldg(&src[e + 3 * nw]), d3 = __ldg(&dst[e + 3 * nw]);
        float4 v0 = __ldg(&reinterpret_cast<const float4*>(h + (size_t)s0 * HID)[lane]);
        float4 v1 = __ldg(&reinterpret_cast<const float4*>(h + (size_t)s1 * HID)[lane]);
        float4 v2 = __ldg(&reinterpret_cast<const float4*>(h + (size_t)s2 * HID)[lane]);
        float4 v3 = __ldg(&reinterpret_cast<const float4*>(h + (size_t)s3 * HID)[lane]);
        red_add_v4(acc + (size_t)d0 * HID + lane * 4, v0);
        red_add_v4(acc + (size_t)d1 * HID + lane * 4, v1);
        red_add_v4(acc + (size_t)d2 * HID + lane * 4, v2);
        red_add_v4(acc + (size_t)d3 * HID + lane * 4, v3);
    }
    for (; e < EE; e += nw) {
        int s0 = __ldg(&src[e]), d0 = __ldg(&dst[e]);
        float4 v0 = __ldg(&reinterpret_cast<const float4*>(h + (size_t)s0 * HID)[lane]);
        red_add_v4(acc + (size_t)d0 * HID + lane * 4, v0);
    }
}

// ---------------------------------------------------------------------------
// launch
// ---------------------------------------------------------------------------
extern "C" void kernel_launch(void* const* d_in, const int* in_sizes, int n_in,
                              void* d_out, int out_size) {
    const float* x   = (const float*)d_in[0];
    const int*   ei  = (const int*)d_in[1];   // int32 edge indices
    const float *W1 = (const float*)d_in[2],  *b1  = (const float*)d_in[3];
    const float *g1 = (const float*)d_in[4],  *be1 = (const float*)d_in[5];
    const float *m1 = (const float*)d_in[6],  *v1  = (const float*)d_in[7];
    const float *W2 = (const float*)d_in[8],  *b2  = (const float*)d_in[9];
    const float *g2 = (const float*)d_in[10], *be2 = (const float*)d_in[11];
    const float *m2 = (const float*)d_in[12], *v2  = (const float*)d_in[13];
    const float *Wc1 = (const float*)d_in[14], *bc1 = (const float*)d_in[15];
    const float *Wc2 = (const float*)d_in[16], *bc2 = (const float*)d_in[17];
    float* out = (float*)d_out;

    const int* src = ei;
    const int* dst = ei + EE;

    float *hb, *ab, *cb;
    cudaGetSymbolAddress((void**)&hb, g_h);
    cudaGetSymbolAddress((void**)&ab, g_acc);
    cudaGetSymbolAddress((void**)&cb, g_cnt);

    const int GB = (NN + 63) / 64;

    // degrees (self loop = 1)
    cnt_init_k<<<(NN + 255) / 256, 256>>>(cb);
    cnt_edge_k<<<(EE + 255) / 256, 256>>>(dst, cb);

    // layer 1: h = x@W1+b1 -> h, acc
    gemm_k<128, false, true, false, false><<<GB, 256>>>(x, W1, b1, hb, ab,
        nullptr, nullptr, nullptr, nullptr, nullptr, nullptr, nullptr);
    scatter_k<<<SC_BLOCKS, 256>>>(src, dst, hb, ab);

    // layer 2: fused finalize(l1) -> GEMM -> h, acc (block-disjoint in-place on acc)
    gemm_k<128, false, true, true, false><<<GB, 256>>>(ab, W2, b2, hb, ab,
        cb, g1, be1, m1, v1, nullptr, nullptr);
    scatter_k<<<SC_BLOCKS, 256>>>(src, dst, hb, ab);

    // classifier: fused finalize(l2) -> GEMM(relu) -> @Wc2 + bc2 -> out [N x 2]
    gemm_k<64, true, false, true, true><<<GB, 256>>>(ab, Wc1, bc1, out, nullptr,
        cb, g2, be2, m2, v2, Wc2, bc2);
}

// round 6
// speedup vs baseline: 1.3428x; 1.0403x over previous
#include <cuda_runtime.h>
#include <cuda_bf16.h>

#define NN 100000
#define EE 1600000
#define HID 128
#define EPSV 1e-5f
#define SCAN_T 1024
#define SCAN_CH 98   /* 1024*98 = 100352 >= NN */

// Scratch (no cudaMalloc allowed).
__device__ float g_h[NN * HID];    // GEMM output h
__device__ float g_acc[NN * HID];  // aggregation output
__device__ int   g_deg[NN];        // edge in-degree (excl. self loop)
__device__ int   g_off[NN + 1];    // CSR offsets
__device__ int   g_cur[NN];        // fill cursors (init = off)
__device__ int   g_adj[EE];        // src ids bucketed by dst

// ---------------------------------------------------------------------------
// CSR build
// ---------------------------------------------------------------------------
__global__ void zero_deg_k(int* deg) {
    int i = blockIdx.x * blockDim.x + threadIdx.x;
    if (i < NN) deg[i] = 0;
}

__global__ void deg_k(const int* __restrict__ dst, int* deg) {
    int e = blockIdx.x * blockDim.x + threadIdx.x;
    if (e < EE) atomicAdd(&deg[dst[e]], 1);
}

// single-block exclusive scan: off[i] = sum_{j<i} deg[j]; cur = off copy
__global__ void __launch_bounds__(SCAN_T) scan_k(const int* __restrict__ deg,
                                                 int* __restrict__ off,
                                                 int* __restrict__ cur) {
    __shared__ int sh[SCAN_T];
    int t = threadIdx.x;
    int lo = t * SCAN_CH;
    int hi = min(lo + SCAN_CH, NN);
    int s = 0;
    for (int i = lo; i < hi; i++) s += deg[i];
    sh[t] = s;
    __syncthreads();
    // Hillis-Steele inclusive scan
    for (int d = 1; d < SCAN_T; d <<= 1) {
        int v = (t >= d) ? sh[t - d] : 0;
        __syncthreads();
        sh[t] += v;
        __syncthreads();
    }
    int base = (t == 0) ? 0 : sh[t - 1];
    for (int i = lo; i < hi; i++) {
        off[i] = base;
        cur[i] = base;
        base += deg[i];
    }
    if (t == SCAN_T - 1) off[NN] = sh[SCAN_T - 1];
}

__global__ void fill_k(const int* __restrict__ src, const int* __restrict__ dst,
                       int* __restrict__ cur, int* __restrict__ adj) {
    int e = blockIdx.x * blockDim.x + threadIdx.x;
    if (e >= EE) return;
    int d = dst[e];
    int p = atomicAdd(&cur[d], 1);
    adj[p] = src[e];
}

// ---------------------------------------------------------------------------
// GEMM: out[N x C] = f(X)[N x 128] @ W[128 x C] + bias   (scalar FFMA)
//   BNIN: f(x_row) = relu((x_row / (deg+1)) * scale + shift)  (fused finalize)
//   CLS:  don't store h; compute h @ Wc2 + bc2 -> out [N x 2]
// ---------------------------------------------------------------------------
template <int C, bool RELU, bool BNIN, bool CLS>
__global__ void __launch_bounds__(256) gemm_k(const float* __restrict__ X,
                                              const float* __restrict__ W,
                                              const float* __restrict__ bias,
                                              float* __restrict__ out,
                                              const int* __restrict__ off,
                                              const float* __restrict__ g,
                                              const float* __restrict__ be,
                                              const float* __restrict__ m,
                                              const float* __restrict__ v,
                                              const float* __restrict__ Wc2,
                                              const float* __restrict__ bc2) {
    constexpr int CG  = C / 4;          // float4 col groups (32 or 16)
    constexpr int RT  = 256 / CG;       // row-thread groups (8 or 16)
    constexpr int RPT = (C == 128) ? 8 : 4;
    constexpr int BM  = RT * RPT;       // 64 rows per block

    __shared__ float xs[BM * 128];
    __shared__ float sc[128];
    __shared__ float sh[128];

    const int row0 = blockIdx.x * BM;
    const int nrow = min(BM, NN - row0);

    if (BNIN) {
        if (threadIdx.x < 128) {
            float s = rsqrtf(v[threadIdx.x] + EPSV) * g[threadIdx.x];
            sc[threadIdx.x] = s;
            sh[threadIdx.x] = be[threadIdx.x] - m[threadIdx.x] * s;
        }
        __syncthreads();
    }

    // coalesced float4 tile load (+ fused mean/BN/ReLU for BNIN)
    {
        const float4* Xv = reinterpret_cast<const float4*>(X + (size_t)row0 * 128);
        float4* xsv = reinterpret_cast<float4*>(xs);
        for (int i = threadIdx.x; i < nrow * 32; i += 256) {
            float4 a = Xv[i];
            if (BNIN) {
                int r = i >> 5;
                int c = (i & 31) * 4;
                int row = row0 + r;
                float ic = 1.0f / (float)(1 + __ldg(&off[row + 1]) - __ldg(&off[row]));
                a.x = fmaxf(fmaf(a.x * ic, sc[c + 0], sh[c + 0]), 0.f);
                a.y = fmaxf(fmaf(a.y * ic, sc[c + 1], sh[c + 1]), 0.f);
                a.z = fmaxf(fmaf(a.z * ic, sc[c + 2], sh[c + 2]), 0.f);
                a.w = fmaxf(fmaf(a.w * ic, sc[c + 3], sh[c + 3]), 0.f);
            }
            xsv[i] = a;
        }
    }
    __syncthreads();

    const int tc = threadIdx.x % CG;    // column group (4 cols)
    const int tr = threadIdx.x / CG;    // row group

    float acc[RPT][4];
#pragma unroll
    for (int r = 0; r < RPT; r++) {
        acc[r][0] = 0.f; acc[r][1] = 0.f; acc[r][2] = 0.f; acc[r][3] = 0.f;
    }

    const float4* Wv = reinterpret_cast<const float4*>(W);
#pragma unroll 4
    for (int k = 0; k < 128; k++) {
        float4 w = __ldg(&Wv[k * CG + tc]);
#pragma unroll
        for (int r = 0; r < RPT; r++) {
            float xv = xs[(tr + r * RT) * 128 + k];
            acc[r][0] = fmaf(xv, w.x, acc[r][0]);
            acc[r][1] = fmaf(xv, w.y, acc[r][1]);
            acc[r][2] = fmaf(xv, w.z, acc[r][2]);
            acc[r][3] = fmaf(xv, w.w, acc[r][3]);
        }
    }

    float4 bv = reinterpret_cast<const float4*>(bias)[tc];
#pragma unroll
    for (int r = 0; r < RPT; r++) {
        int row = row0 + tr + r * RT;
        float h0 = acc[r][0] + bv.x;
        float h1 = acc[r][1] + bv.y;
        float h2 = acc[r][2] + bv.z;
        float h3 = acc[r][3] + bv.w;
        if (RELU) {
            h0 = fmaxf(h0, 0.f); h1 = fmaxf(h1, 0.f);
            h2 = fmaxf(h2, 0.f); h3 = fmaxf(h3, 0.f);
        }
        if (CLS) {
            int c0 = tc * 4;
            float p0 = h0 * __ldg(&Wc2[(c0 + 0) * 2])     + h1 * __ldg(&Wc2[(c0 + 1) * 2])
                     + h2 * __ldg(&Wc2[(c0 + 2) * 2])     + h3 * __ldg(&Wc2[(c0 + 3) * 2]);
            float p1 = h0 * __ldg(&Wc2[(c0 + 0) * 2 + 1]) + h1 * __ldg(&Wc2[(c0 + 1) * 2 + 1])
                     + h2 * __ldg(&Wc2[(c0 + 2) * 2 + 1]) + h3 * __ldg(&Wc2[(c0 + 3) * 2 + 1]);
#pragma unroll
            for (int o = CG / 2; o; o >>= 1) {
                p0 += __shfl_xor_sync(0xffffffffu, p0, o);
                p1 += __shfl_xor_sync(0xffffffffu, p1, o);
            }
            if (tc == 0 && row < NN) {
                out[(size_t)row * 2 + 0] = p0 + bc2[0];
                out[(size_t)row * 2 + 1] = p1 + bc2[1];
            }
        } else if (row < NN) {
            float4 o = {h0, h1, h2, h3};
            reinterpret_cast<float4*>(out + (size_t)row * C)[tc] = o;
        }
    }
}

// ---------------------------------------------------------------------------
// pull aggregation: warp per node, acc[node] = h[node] + sum_{s in adj} h[s]
// ---------------------------------------------------------------------------
__global__ void __launch_bounds__(256) agg_k(const int* __restrict__ adj,
                                             const int* __restrict__ off,
                                             const float* __restrict__ h,
                                             float* __restrict__ acc) {
    int node = (blockIdx.x * 256 + threadIdx.x) >> 5;
    int lane = threadIdx.x & 31;
    if (node >= NN) return;

    int beg = __ldg(&off[node]);
    int end = __ldg(&off[node + 1]);

    const float4* hv = reinterpret_cast<const float4*>(h);
    float4 a = __ldg(&hv[(size_t)node * 32 + lane]);   // self loop

    int i = beg;
    for (; i + 4 <= end; i += 4) {
        int s0 = __ldg(&adj[i]);
        int s1 = __ldg(&adj[i + 1]);
        int s2 = __ldg(&adj[i + 2]);
        int s3 = __ldg(&adj[i + 3]);
        float4 v0 = __ldg(&hv[(size_t)s0 * 32 + lane]);
        float4 v1 = __ldg(&hv[(size_t)s1 * 32 + lane]);
        float4 v2 = __ldg(&hv[(size_t)s2 * 32 + lane]);
        float4 v3 = __ldg(&hv[(size_t)s3 * 32 + lane]);
        float4 t0 = {v0.x + v1.x, v0.y + v1.y, v0.z + v1.z, v0.w + v1.w};
        float4 t1 = {v2.x + v3.x, v2.y + v3.y, v2.z + v3.z, v2.w + v3.w};
        a.x += t0.x + t1.x;
        a.y += t0.y + t1.y;
        a.z += t0.z + t1.z;
        a.w += t0.w + t1.w;
    }
    for (; i < end; i++) {
        int s = __ldg(&adj[i]);
        float4 v = __ldg(&hv[(size_t)s * 32 + lane]);
        a.x += v.x; a.y += v.y; a.z += v.z; a.w += v.w;
    }

    reinterpret_cast<float4*>(acc)[(size_t)node * 32 + lane] = a;
}

// ---------------------------------------------------------------------------
// launch
// ---------------------------------------------------------------------------
extern "C" void kernel_launch(void* const* d_in, const int* in_sizes, int n_in,
                              void* d_out, int out_size) {
    const float* x   = (const float*)d_in[0];
    const int*   ei  = (const int*)d_in[1];   // int32 edge indices
    const float *W1 = (const float*)d_in[2],  *b1  = (const float*)d_in[3];
    const float *g1 = (const float*)d_in[4],  *be1 = (const float*)d_in[5];
    const float *m1 = (const float*)d_in[6],  *v1  = (const float*)d_in[7];
    const float *W2 = (const float*)d_in[8],  *b2  = (const float*)d_in[9];
    const float *g2 = (const float*)d_in[10], *be2 = (const float*)d_in[11];
    const float *m2 = (const float*)d_in[12], *v2  = (const float*)d_in[13];
    const float *Wc1 = (const float*)d_in[14], *bc1 = (const float*)d_in[15];
    const float *Wc2 = (const float*)d_in[16], *bc2 = (const float*)d_in[17];
    float* out = (float*)d_out;

    const int* src = ei;
    const int* dst = ei + EE;

    float *hb, *ab;
    int *degb, *offb, *curb, *adjb;
    cudaGetSymbolAddress((void**)&hb, g_h);
    cudaGetSymbolAddress((void**)&ab, g_acc);
    cudaGetSymbolAddress((void**)&degb, g_deg);
    cudaGetSymbolAddress((void**)&offb, g_off);
    cudaGetSymbolAddress((void**)&curb, g_cur);
    cudaGetSymbolAddress((void**)&adjb, g_adj);

    const int GB = (NN + 63) / 64;
    const int AB = (NN * 32 + 255) / 256;   // agg: warp per node

    // CSR build
    zero_deg_k<<<(NN + 255) / 256, 256>>>(degb);
    deg_k<<<(EE + 255) / 256, 256>>>(dst, degb);
    scan_k<<<1, SCAN_T>>>(degb, offb, curb);
    fill_k<<<(EE + 255) / 256, 256>>>(src, dst, curb, adjb);

    // layer 1
    gemm_k<128, false, false, false><<<GB, 256>>>(x, W1, b1, hb,
        nullptr, nullptr, nullptr, nullptr, nullptr, nullptr, nullptr);
    agg_k<<<AB, 256>>>(adjb, offb, hb, ab);

    // layer 2 (finalize of layer 1 fused into GEMM input)
    gemm_k<128, false, true, false><<<GB, 256>>>(ab, W2, b2, hb,
        offb, g1, be1, m1, v1, nullptr, nullptr);
    agg_k<<<AB, 256>>>(adjb, offb, hb, ab);

    // classifier (finalize of layer 2 + Wc1 GEMM + Wc2 tail fused)
    gemm_k<64, true, true, true><<<GB, 256>>>(ab, Wc1, bc1, out,
        offb, g2, be2, m2, v2, Wc2, bc2);
}

// round 7
// speedup vs baseline: 1.4248x; 1.0611x over previous
#include <cuda_runtime.h>
#include <cuda_bf16.h>

#define NN 100000
#define EE 1600000
#define HID 128
#define EPSV 1e-5f
#define SCAN_T 1024
#define SCAN_CH 98   /* 1024*98 = 100352 >= NN */

typedef unsigned long long u64;
typedef unsigned int u32;

// Scratch (no cudaMalloc allowed).
__device__ float g_h[NN * HID];    // GEMM output h
__device__ float g_acc[NN * HID];  // aggregation output
__device__ int   g_deg[NN];        // edge in-degree (excl. self loop)
__device__ int   g_off[NN + 1];    // CSR offsets
__device__ int   g_cur[NN];        // fill cursors (init = off)
__device__ int   g_adj[EE];        // src ids bucketed by dst

// ---------------------------------------------------------------------------
// f32x2 helpers
// ---------------------------------------------------------------------------
__device__ __forceinline__ void fma2(u64& d, u64 a, u64 b) {
    asm("fma.rn.f32x2 %0, %1, %2, %0;" : "+l"(d) : "l"(a), "l"(b));
}
__device__ __forceinline__ u64 packf2(float lo, float hi) {
    return (u64)__float_as_uint(lo) | ((u64)__float_as_uint(hi) << 32);
}
__device__ __forceinline__ float sum2(u64 p) {
    return __uint_as_float((u32)p) + __uint_as_float((u32)(p >> 32));
}

// ---------------------------------------------------------------------------
// CSR build
// ---------------------------------------------------------------------------
__global__ void zero_deg_k(int* deg) {
    int i = blockIdx.x * blockDim.x + threadIdx.x;
    if (i < NN) deg[i] = 0;
}

__global__ void deg_k(const int* __restrict__ dst, int* deg) {
    int e = blockIdx.x * blockDim.x + threadIdx.x;
    if (e < EE) atomicAdd(&deg[dst[e]], 1);
}

__global__ void __launch_bounds__(SCAN_T) scan_k(const int* __restrict__ deg,
                                                 int* __restrict__ off,
                                                 int* __restrict__ cur) {
    __shared__ int sh[SCAN_T];
    int t = threadIdx.x;
    int lo = t * SCAN_CH;
    int hi = min(lo + SCAN_CH, NN);
    int s = 0;
    for (int i = lo; i < hi; i++) s += deg[i];
    sh[t] = s;
    __syncthreads();
    for (int d = 1; d < SCAN_T; d <<= 1) {
        int v = (t >= d) ? sh[t - d] : 0;
        __syncthreads();
        sh[t] += v;
        __syncthreads();
    }
    int base = (t == 0) ? 0 : sh[t - 1];
    for (int i = lo; i < hi; i++) {
        off[i] = base;
        cur[i] = base;
        base += deg[i];
    }
    if (t == SCAN_T - 1) off[NN] = sh[SCAN_T - 1];
}

__global__ void fill_k(const int* __restrict__ src, const int* __restrict__ dst,
                       int* __restrict__ cur, int* __restrict__ adj) {
    int e = blockIdx.x * blockDim.x + threadIdx.x;
    if (e >= EE) return;
    int d = dst[e];
    int p = atomicAdd(&cur[d], 1);
    adj[p] = src[e];
}

// ---------------------------------------------------------------------------
// GEMM: out[N x C] = f(X)[N x 128] @ W[128 x C] + bias
// f32x2 inner loop: W pre-packed over k-pairs in smem, x pairs via LDS.64.
// Thread owns cols {tc + c*CG, c=0..3} and RPT rows.
//   BNIN: f(x_row) = relu((x_row / (deg+1)) * scale + shift)
//   CLS:  don't store h; compute h @ Wc2 + bc2 -> out [N x 2]
// ---------------------------------------------------------------------------
template <int C, bool RELU, bool BNIN, bool CLS>
__global__ void __launch_bounds__(256) gemm_k(const float* __restrict__ X,
                                              const float* __restrict__ W,
                                              const float* __restrict__ bias,
                                              float* __restrict__ out,
                                              const int* __restrict__ off,
                                              const float* __restrict__ g,
                                              const float* __restrict__ be,
                                              const float* __restrict__ m,
                                              const float* __restrict__ v,
                                              const float* __restrict__ Wc2,
                                              const float* __restrict__ bc2) {
    constexpr int CG  = C / 4;          // threads per row-group (32 or 16)
    constexpr int RT  = 256 / CG;       // row groups (8 or 16)
    constexpr int RPT = (C == 128) ? 8 : 4;
    constexpr int BM  = RT * RPT;       // 64 rows per block

    extern __shared__ char smraw[];
    float* xs = (float*)smraw;                                   // BM*128 f32
    u64*   ws = (u64*)(smraw + BM * 128 * sizeof(float));        // 64*C u64
    float* sc = (float*)(smraw + BM * 128 * 4 + 64 * C * 8);     // 128 f32
    float* sh = sc + 128;                                        // 128 f32

    const int row0 = blockIdx.x * BM;
    const int nrow = min(BM, NN - row0);

    if (BNIN && threadIdx.x < 128) {
        float s = rsqrtf(v[threadIdx.x] + EPSV) * g[threadIdx.x];
        sc[threadIdx.x] = s;
        sh[threadIdx.x] = be[threadIdx.x] - m[threadIdx.x] * s;
    }

    // pack W k-pairs: ws[kk*C + col] = (W[2kk][col], W[2kk+1][col])
    for (int idx = threadIdx.x; idx < 64 * C; idx += 256) {
        int kk = idx / C, col = idx % C;
        ws[idx] = packf2(__ldg(&W[(2 * kk) * C + col]), __ldg(&W[(2 * kk + 1) * C + col]));
    }

    if (BNIN) __syncthreads();   // sc/sh ready before tile transform

    // coalesced float4 tile load (+ fused mean/BN/ReLU for BNIN)
    {
        const float4* Xv = reinterpret_cast<const float4*>(X + (size_t)row0 * 128);
        float4* xsv = reinterpret_cast<float4*>(xs);
        for (int i = threadIdx.x; i < nrow * 32; i += 256) {
            float4 a = Xv[i];
            if (BNIN) {
                int r = i >> 5;
                int c = (i & 31) * 4;
                int row = row0 + r;
                float ic = 1.0f / (float)(1 + __ldg(&off[row + 1]) - __ldg(&off[row]));
                a.x = fmaxf(fmaf(a.x * ic, sc[c + 0], sh[c + 0]), 0.f);
                a.y = fmaxf(fmaf(a.y * ic, sc[c + 1], sh[c + 1]), 0.f);
                a.z = fmaxf(fmaf(a.z * ic, sc[c + 2], sh[c + 2]), 0.f);
                a.w = fmaxf(fmaf(a.w * ic, sc[c + 3], sh[c + 3]), 0.f);
            }
            xsv[i] = a;
        }
    }
    __syncthreads();   // xs + ws ready

    const int tc = threadIdx.x % CG;
    const int tr = threadIdx.x / CG;

    u64 acc2[RPT][4];
#pragma unroll
    for (int r = 0; r < RPT; r++)
#pragma unroll
        for (int c = 0; c < 4; c++) acc2[r][c] = 0ULL;

#pragma unroll 2
    for (int kk = 0; kk < 64; kk++) {
        u64 wp0 = ws[kk * C + tc];
        u64 wp1 = ws[kk * C + tc + CG];
        u64 wp2 = ws[kk * C + tc + 2 * CG];
        u64 wp3 = ws[kk * C + tc + 3 * CG];
#pragma unroll
        for (int r = 0; r < RPT; r++) {
            u64 xp = *reinterpret_cast<const u64*>(xs + (tr + r * RT) * 128 + 2 * kk);
            fma2(acc2[r][0], xp, wp0);
            fma2(acc2[r][1], xp, wp1);
            fma2(acc2[r][2], xp, wp2);
            fma2(acc2[r][3], xp, wp3);
        }
    }

    float bv0 = __ldg(&bias[tc]);
    float bv1 = __ldg(&bias[tc + CG]);
    float bv2 = __ldg(&bias[tc + 2 * CG]);
    float bv3 = __ldg(&bias[tc + 3 * CG]);

#pragma unroll
    for (int r = 0; r < RPT; r++) {
        int row = row0 + tr + r * RT;
        float h0 = sum2(acc2[r][0]) + bv0;
        float h1 = sum2(acc2[r][1]) + bv1;
        float h2 = sum2(acc2[r][2]) + bv2;
        float h3 = sum2(acc2[r][3]) + bv3;
        if (RELU) {
            h0 = fmaxf(h0, 0.f); h1 = fmaxf(h1, 0.f);
            h2 = fmaxf(h2, 0.f); h3 = fmaxf(h3, 0.f);
        }
        if (CLS) {
            float p0 = h0 * __ldg(&Wc2[tc * 2])                + h1 * __ldg(&Wc2[(tc + CG) * 2])
                     + h2 * __ldg(&Wc2[(tc + 2 * CG) * 2])     + h3 * __ldg(&Wc2[(tc + 3 * CG) * 2]);
            float p1 = h0 * __ldg(&Wc2[tc * 2 + 1])            + h1 * __ldg(&Wc2[(tc + CG) * 2 + 1])
                     + h2 * __ldg(&Wc2[(tc + 2 * CG) * 2 + 1]) + h3 * __ldg(&Wc2[(tc + 3 * CG) * 2 + 1]);
#pragma unroll
            for (int o = CG / 2; o; o >>= 1) {
                p0 += __shfl_xor_sync(0xffffffffu, p0, o);
                p1 += __shfl_xor_sync(0xffffffffu, p1, o);
            }
            if (tc == 0 && row < NN) {
                out[(size_t)row * 2 + 0] = p0 + bc2[0];
                out[(size_t)row * 2 + 1] = p1 + bc2[1];
            }
        } else if (row < NN) {
            float* orow = out + (size_t)row * C;
            orow[tc]          = h0;
            orow[tc + CG]     = h1;
            orow[tc + 2 * CG] = h2;
            orow[tc + 3 * CG] = h3;
        }
    }
}

// ---------------------------------------------------------------------------
// pull aggregation: warp per node, 8-deep pipelined gathers, dual accumulators
// ---------------------------------------------------------------------------
__global__ void __launch_bounds__(256) agg_k(const int* __restrict__ adj,
                                             const int* __restrict__ off,
                                             const float* __restrict__ h,
                                             float* __restrict__ acc) {
    int node = (blockIdx.x * 256 + threadIdx.x) >> 5;
    int lane = threadIdx.x & 31;
    if (node >= NN) return;

    int beg = __ldg(&off[node]);
    int end = __ldg(&off[node + 1]);

    const float4* hv = reinterpret_cast<const float4*>(h);
    float4 a0 = __ldg(&hv[(size_t)node * 32 + lane]);   // self loop
    float4 a1 = {0.f, 0.f, 0.f, 0.f};

    int i = beg;
    for (; i + 8 <= end; i += 8) {
        int s0 = __ldg(&adj[i]),     s1 = __ldg(&adj[i + 1]);
        int s2 = __ldg(&adj[i + 2]), s3 = __ldg(&adj[i + 3]);
        int s4 = __ldg(&adj[i + 4]), s5 = __ldg(&adj[i + 5]);
        int s6 = __ldg(&adj[i + 6]), s7 = __ldg(&adj[i + 7]);
        float4 v0 = __ldg(&hv[(size_t)s0 * 32 + lane]);
        float4 v1 = __ldg(&hv[(size_t)s1 * 32 + lane]);
        float4 v2 = __ldg(&hv[(size_t)s2 * 32 + lane]);
        float4 v3 = __ldg(&hv[(size_t)s3 * 32 + lane]);
        float4 v4 = __ldg(&hv[(size_t)s4 * 32 + lane]);
        float4 v5 = __ldg(&hv[(size_t)s5 * 32 + lane]);
        float4 v6 = __ldg(&hv[(size_t)s6 * 32 + lane]);
        float4 v7 = __ldg(&hv[(size_t)s7 * 32 + lane]);
        a0.x += (v0.x + v1.x) + (v2.x + v3.x);
        a0.y += (v0.y + v1.y) + (v2.y + v3.y);
        a0.z += (v0.z + v1.z) + (v2.z + v3.z);
        a0.w += (v0.w + v1.w) + (v2.w + v3.w);
        a1.x += (v4.x + v5.x) + (v6.x + v7.x);
        a1.y += (v4.y + v5.y) + (v6.y + v7.y);
        a1.z += (v4.z + v5.z) + (v6.z + v7.z);
        a1.w += (v4.w + v5.w) + (v6.w + v7.w);
    }
    for (; i + 4 <= end; i += 4) {
        int s0 = __ldg(&adj[i]),     s1 = __ldg(&adj[i + 1]);
        int s2 = __ldg(&adj[i + 2]), s3 = __ldg(&adj[i + 3]);
        float4 v0 = __ldg(&hv[(size_t)s0 * 32 + lane]);
        float4 v1 = __ldg(&hv[(size_t)s1 * 32 + lane]);
        float4 v2 = __ldg(&hv[(size_t)s2 * 32 + lane]);
        float4 v3 = __ldg(&hv[(size_t)s3 * 32 + lane]);
        a0.x += (v0.x + v1.x) + (v2.x + v3.x);
        a0.y += (v0.y + v1.y) + (v2.y + v3.y);
        a0.z += (v0.z + v1.z) + (v2.z + v3.z);
        a0.w += (v0.w + v1.w) + (v2.w + v3.w);
    }
    for (; i < end; i++) {
        int s = __ldg(&adj[i]);
        float4 vv = __ldg(&hv[(size_t)s * 32 + lane]);
        a1.x += vv.x; a1.y += vv.y; a1.z += vv.z; a1.w += vv.w;
    }

    float4 a = {a0.x + a1.x, a0.y + a1.y, a0.z + a1.z, a0.w + a1.w};
    reinterpret_cast<float4*>(acc)[(size_t)node * 32 + lane] = a;
}

// ---------------------------------------------------------------------------
// launch
// ---------------------------------------------------------------------------
extern "C" void kernel_launch(void* const* d_in, const int* in_sizes, int n_in,
                              void* d_out, int out_size) {
    const float* x   = (const float*)d_in[0];
    const int*   ei  = (const int*)d_in[1];   // int32 edge indices
    const float *W1 = (const float*)d_in[2],  *b1  = (const float*)d_in[3];
    const float *g1 = (const float*)d_in[4],  *be1 = (const float*)d_in[5];
    const float *m1 = (const float*)d_in[6],  *v1  = (const float*)d_in[7];
    const float *W2 = (const float*)d_in[8],  *b2  = (const float*)d_in[9];
    const float *g2 = (const float*)d_in[10], *be2 = (const float*)d_in[11];
    const float *m2 = (const float*)d_in[12], *v2  = (const float*)d_in[13];
    const float *Wc1 = (const float*)d_in[14], *bc1 = (const float*)d_in[15];
    const float *Wc2 = (const float*)d_in[16], *bc2 = (const float*)d_in[17];
    float* out = (float*)d_out;

    const int* src = ei;
    const int* dst = ei + EE;

    float *hb, *ab;
    int *degb, *offb, *curb, *adjb;
    cudaGetSymbolAddress((void**)&hb, g_h);
    cudaGetSymbolAddress((void**)&ab, g_acc);
    cudaGetSymbolAddress((void**)&degb, g_deg);
    cudaGetSymbolAddress((void**)&offb, g_off);
    cudaGetSymbolAddress((void**)&curb, g_cur);
    cudaGetSymbolAddress((void**)&adjb, g_adj);

    const int GB = (NN + 63) / 64;
    const int AB = (NN * 32 + 255) / 256;

    const int SM128 = 64 * 128 * 4 + 64 * 128 * 8 + 1024;  // 99328
    const int SM64  = 64 * 128 * 4 + 64 * 64 * 8 + 1024;   // 66560

    cudaFuncSetAttribute(gemm_k<128, false, false, false>,
                         cudaFuncAttributeMaxDynamicSharedMemorySize, SM128);
    cudaFuncSetAttribute(gemm_k<128, false, true, false>,
                         cudaFuncAttributeMaxDynamicSharedMemorySize, SM128);
    cudaFuncSetAttribute(gemm_k<64, true, true, true>,
                         cudaFuncAttributeMaxDynamicSharedMemorySize, SM64);

    // CSR build
    zero_deg_k<<<(NN + 255) / 256, 256>>>(degb);
    deg_k<<<(EE + 255) / 256, 256>>>(dst, degb);
    scan_k<<<1, SCAN_T>>>(degb, offb, curb);
    fill_k<<<(EE + 255) / 256, 256>>>(src, dst, curb, adjb);

    // layer 1
    gemm_k<128, false, false, false><<<GB, 256, SM128>>>(x, W1, b1, hb,
        nullptr, nullptr, nullptr, nullptr, nullptr, nullptr, nullptr);
    agg_k<<<AB, 256>>>(adjb, offb, hb, ab);

    // layer 2 (finalize of layer 1 fused into GEMM input)
    gemm_k<128, false, true, false><<<GB, 256, SM128>>>(ab, W2, b2, hb,
        offb, g1, be1, m1, v1, nullptr, nullptr);
    agg_k<<<AB, 256>>>(adjb, offb, hb, ab);

    // classifier (finalize of layer 2 + Wc1 GEMM + Wc2 tail fused)
    gemm_k<64, true, true, true><<<GB, 256, SM64>>>(ab, Wc1, bc1, out,
        offb, g2, be2, m2, v2, Wc2, bc2);
}

// round 8
// speedup vs baseline: 1.5183x; 1.0656x over previous
#include <cuda_runtime.h>
#include <cuda_fp16.h>

#define NN 100000
#define EE 1600000
#define HID 128
#define EPSV 1e-5f
#define SCAN_T 1024
#define SCAN_CH 98   /* 1024*98 = 100352 >= NN */

typedef unsigned long long u64;
typedef unsigned int u32;

// Scratch (no cudaMalloc allowed).
__device__ __half g_hh[NN * HID];  // GEMM output h (fp16 for cheap gathers)
__device__ float  g_acc[NN * HID]; // aggregation output (fp32)
__device__ int    g_deg[NN];
__device__ int    g_off[NN + 1];
__device__ int    g_cur[NN];
__device__ int    g_adj[EE];

// ---------------------------------------------------------------------------
// f32x2 helpers
// ---------------------------------------------------------------------------
__device__ __forceinline__ void fma2(u64& d, u64 a, u64 b) {
    asm("fma.rn.f32x2 %0, %1, %2, %0;" : "+l"(d) : "l"(a), "l"(b));
}
__device__ __forceinline__ u64 packf2(float lo, float hi) {
    return (u64)__float_as_uint(lo) | ((u64)__float_as_uint(hi) << 32);
}
__device__ __forceinline__ float sum2(u64 p) {
    return __uint_as_float((u32)p) + __uint_as_float((u32)(p >> 32));
}

// ---------------------------------------------------------------------------
// CSR build
// ---------------------------------------------------------------------------
__global__ void zero_deg_k(int* deg) {
    int i = blockIdx.x * blockDim.x + threadIdx.x;
    if (i < NN) deg[i] = 0;
}

__global__ void deg_k(const int* __restrict__ dst, int* deg) {
    int e = blockIdx.x * blockDim.x + threadIdx.x;
    if (e < EE) atomicAdd(&deg[dst[e]], 1);
}

__global__ void __launch_bounds__(SCAN_T) scan_k(const int* __restrict__ deg,
                                                 int* __restrict__ off,
                                                 int* __restrict__ cur) {
    __shared__ int sh[SCAN_T];
    int t = threadIdx.x;
    int lo = t * SCAN_CH;
    int hi = min(lo + SCAN_CH, NN);
    int s = 0;
    for (int i = lo; i < hi; i++) s += deg[i];
    sh[t] = s;
    __syncthreads();
    for (int d = 1; d < SCAN_T; d <<= 1) {
        int v = (t >= d) ? sh[t - d] : 0;
        __syncthreads();
        sh[t] += v;
        __syncthreads();
    }
    int base = (t == 0) ? 0 : sh[t - 1];
    for (int i = lo; i < hi; i++) {
        off[i] = base;
        cur[i] = base;
        base += deg[i];
    }
    if (t == SCAN_T - 1) off[NN] = sh[SCAN_T - 1];
}

__global__ void fill_k(const int* __restrict__ src, const int* __restrict__ dst,
                       int* __restrict__ cur, int* __restrict__ adj) {
    int e = blockIdx.x * blockDim.x + threadIdx.x;
    if (e >= EE) return;
    int d = dst[e];
    int p = atomicAdd(&cur[d], 1);
    adj[p] = src[e];
}

// ---------------------------------------------------------------------------
// GEMM: out[N x C] = f(X)[N x 128] @ W[128 x C] + bias
// f32x2 inner loop (W pre-packed k-pairs in smem, x pairs via LDS.64).
//   BNIN: f(x_row) = relu((x_row / (deg+1)) * scale + shift)
//   CLS:  compute h @ Wc2 + bc2 -> outf [N x 2] (fp32)
//   else: store h as fp16 into outh
// ---------------------------------------------------------------------------
template <int C, bool RELU, bool BNIN, bool CLS>
__global__ void __launch_bounds__(256) gemm_k(const float* __restrict__ X,
                                              const float* __restrict__ W,
                                              const float* __restrict__ bias,
                                              __half* __restrict__ outh,
                                              float* __restrict__ outf,
                                              const int* __restrict__ off,
                                              const float* __restrict__ g,
                                              const float* __restrict__ be,
                                              const float* __restrict__ m,
                                              const float* __restrict__ v,
                                              const float* __restrict__ Wc2,
                                              const float* __restrict__ bc2) {
    constexpr int CG  = C / 4;
    constexpr int RT  = 256 / CG;
    constexpr int RPT = (C == 128) ? 8 : 4;
    constexpr int BM  = RT * RPT;       // 64

    extern __shared__ char smraw[];
    float* xs = (float*)smraw;                                   // BM*128 f32
    u64*   ws = (u64*)(smraw + BM * 128 * sizeof(float));        // 64*C u64
    float* sc = (float*)(smraw + BM * 128 * 4 + 64 * C * 8);     // 128 f32
    float* sh = sc + 128;

    const int row0 = blockIdx.x * BM;
    const int nrow = min(BM, NN - row0);

    if (BNIN && threadIdx.x < 128) {
        float s = rsqrtf(v[threadIdx.x] + EPSV) * g[threadIdx.x];
        sc[threadIdx.x] = s;
        sh[threadIdx.x] = be[threadIdx.x] - m[threadIdx.x] * s;
    }

    for (int idx = threadIdx.x; idx < 64 * C; idx += 256) {
        int kk = idx / C, col = idx % C;
        ws[idx] = packf2(__ldg(&W[(2 * kk) * C + col]), __ldg(&W[(2 * kk + 1) * C + col]));
    }

    if (BNIN) __syncthreads();

    {
        const float4* Xv = reinterpret_cast<const float4*>(X + (size_t)row0 * 128);
        float4* xsv = reinterpret_cast<float4*>(xs);
        for (int i = threadIdx.x; i < nrow * 32; i += 256) {
            float4 a = Xv[i];
            if (BNIN) {
                int r = i >> 5;
                int c = (i & 31) * 4;
                int row = row0 + r;
                float ic = 1.0f / (float)(1 + __ldg(&off[row + 1]) - __ldg(&off[row]));
                a.x = fmaxf(fmaf(a.x * ic, sc[c + 0], sh[c + 0]), 0.f);
                a.y = fmaxf(fmaf(a.y * ic, sc[c + 1], sh[c + 1]), 0.f);
                a.z = fmaxf(fmaf(a.z * ic, sc[c + 2], sh[c + 2]), 0.f);
                a.w = fmaxf(fmaf(a.w * ic, sc[c + 3], sh[c + 3]), 0.f);
            }
            xsv[i] = a;
        }
    }
    __syncthreads();

    const int tc = threadIdx.x % CG;
    const int tr = threadIdx.x / CG;

    u64 acc2[RPT][4];
#pragma unroll
    for (int r = 0; r < RPT; r++)
#pragma unroll
        for (int c = 0; c < 4; c++) acc2[r][c] = 0ULL;

#pragma unroll 2
    for (int kk = 0; kk < 64; kk++) {
        u64 wp0 = ws[kk * C + tc];
        u64 wp1 = ws[kk * C + tc + CG];
        u64 wp2 = ws[kk * C + tc + 2 * CG];
        u64 wp3 = ws[kk * C + tc + 3 * CG];
#pragma unroll
        for (int r = 0; r < RPT; r++) {
            u64 xp = *reinterpret_cast<const u64*>(xs + (tr + r * RT) * 128 + 2 * kk);
            fma2(acc2[r][0], xp, wp0);
            fma2(acc2[r][1], xp, wp1);
            fma2(acc2[r][2], xp, wp2);
            fma2(acc2[r][3], xp, wp3);
        }
    }

    float bv0 = __ldg(&bias[tc]);
    float bv1 = __ldg(&bias[tc + CG]);
    float bv2 = __ldg(&bias[tc + 2 * CG]);
    float bv3 = __ldg(&bias[tc + 3 * CG]);

#pragma unroll
    for (int r = 0; r < RPT; r++) {
        int row = row0 + tr + r * RT;
        float h0 = sum2(acc2[r][0]) + bv0;
        float h1 = sum2(acc2[r][1]) + bv1;
        float h2 = sum2(acc2[r][2]) + bv2;
        float h3 = sum2(acc2[r][3]) + bv3;
        if (RELU) {
            h0 = fmaxf(h0, 0.f); h1 = fmaxf(h1, 0.f);
            h2 = fmaxf(h2, 0.f); h3 = fmaxf(h3, 0.f);
        }
        if (CLS) {
            float p0 = h0 * __ldg(&Wc2[tc * 2])                + h1 * __ldg(&Wc2[(tc + CG) * 2])
                     + h2 * __ldg(&Wc2[(tc + 2 * CG) * 2])     + h3 * __ldg(&Wc2[(tc + 3 * CG) * 2]);
            float p1 = h0 * __ldg(&Wc2[tc * 2 + 1])            + h1 * __ldg(&Wc2[(tc + CG) * 2 + 1])
                     + h2 * __ldg(&Wc2[(tc + 2 * CG) * 2 + 1]) + h3 * __ldg(&Wc2[(tc + 3 * CG) * 2 + 1]);
#pragma unroll
            for (int o = CG / 2; o; o >>= 1) {
                p0 += __shfl_xor_sync(0xffffffffu, p0, o);
                p1 += __shfl_xor_sync(0xffffffffu, p1, o);
            }
            if (tc == 0 && row < NN) {
                outf[(size_t)row * 2 + 0] = p0 + bc2[0];
                outf[(size_t)row * 2 + 1] = p1 + bc2[1];
            }
        } else if (row < NN) {
            __half* orow = outh + (size_t)row * C;
            orow[tc]          = __float2half(h0);
            orow[tc + CG]     = __float2half(h1);
            orow[tc + 2 * CG] = __float2half(h2);
            orow[tc + 3 * CG] = __float2half(h3);
        }
    }
}

// ---------------------------------------------------------------------------
// pull aggregation: warp per node; h in fp16 (256 B/row gather), fp32 accum
// lane owns cols [4*lane, 4*lane+4) = one uint2 (4 halves)
// ---------------------------------------------------------------------------
__device__ __forceinline__ float4 h4_to_f4(uint2 u) {
    __half2 p0 = *reinterpret_cast<__half2*>(&u.x);
    __half2 p1 = *reinterpret_cast<__half2*>(&u.y);
    float2 f0 = __half22float2(p0);
    float2 f1 = __half22float2(p1);
    return make_float4(f0.x, f0.y, f1.x, f1.y);
}

__global__ void __launch_bounds__(256) agg_k(const int* __restrict__ adj,
                                             const int* __restrict__ off,
                                             const __half* __restrict__ h,
                                             float* __restrict__ acc) {
    int node = (blockIdx.x * 256 + threadIdx.x) >> 5;
    int lane = threadIdx.x & 31;
    if (node >= NN) return;

    int beg = __ldg(&off[node]);
    int end = __ldg(&off[node + 1]);

    const uint2* hv = reinterpret_cast<const uint2*>(h);
    float4 a0 = h4_to_f4(__ldg(&hv[(size_t)node * 32 + lane]));   // self loop
    float4 a1 = {0.f, 0.f, 0.f, 0.f};

    int i = beg;
    for (; i + 8 <= end; i += 8) {
        int s0 = __ldg(&adj[i]),     s1 = __ldg(&adj[i + 1]);
        int s2 = __ldg(&adj[i + 2]), s3 = __ldg(&adj[i + 3]);
        int s4 = __ldg(&adj[i + 4]), s5 = __ldg(&adj[i + 5]);
        int s6 = __ldg(&adj[i + 6]), s7 = __ldg(&adj[i + 7]);
        float4 v0 = h4_to_f4(__ldg(&hv[(size_t)s0 * 32 + lane]));
        float4 v1 = h4_to_f4(__ldg(&hv[(size_t)s1 * 32 + lane]));
        float4 v2 = h4_to_f4(__ldg(&hv[(size_t)s2 * 32 + lane]));
        float4 v3 = h4_to_f4(__ldg(&hv[(size_t)s3 * 32 + lane]));
        float4 v4 = h4_to_f4(__ldg(&hv[(size_t)s4 * 32 + lane]));
        float4 v5 = h4_to_f4(__ldg(&hv[(size_t)s5 * 32 + lane]));
        float4 v6 = h4_to_f4(__ldg(&hv[(size_t)s6 * 32 + lane]));
        float4 v7 = h4_to_f4(__ldg(&hv[(size_t)s7 * 32 + lane]));
        a0.x += (v0.x + v1.x) + (v2.x + v3.x);
        a0.y += (v0.y + v1.y) + (v2.y + v3.y);
        a0.z += (v0.z + v1.z) + (v2.z + v3.z);
        a0.w += (v0.w + v1.w) + (v2.w + v3.w);
        a1.x += (v4.x + v5.x) + (v6.x + v7.x);
        a1.y += (v4.y + v5.y) + (v6.y + v7.y);
        a1.z += (v4.z + v5.z) + (v6.z + v7.z);
        a1.w += (v4.w + v5.w) + (v6.w + v7.w);
    }
    for (; i + 4 <= end; i += 4) {
        int s0 = __ldg(&adj[i]),     s1 = __ldg(&adj[i + 1]);
        int s2 = __ldg(&adj[i + 2]), s3 = __ldg(&adj[i + 3]);
        float4 v0 = h4_to_f4(__ldg(&hv[(size_t)s0 * 32 + lane]));
        float4 v1 = h4_to_f4(__ldg(&hv[(size_t)s1 * 32 + lane]));
        float4 v2 = h4_to_f4(__ldg(&hv[(size_t)s2 * 32 + lane]));
        float4 v3 = h4_to_f4(__ldg(&hv[(size_t)s3 * 32 + lane]));
        a0.x += (v0.x + v1.x) + (v2.x + v3.x);
        a0.y += (v0.y + v1.y) + (v2.y + v3.y);
        a0.z += (v0.z + v1.z) + (v2.z + v3.z);
        a0.w += (v0.w + v1.w) + (v2.w + v3.w);
    }
    for (; i < end; i++) {
        int s = __ldg(&adj[i]);
        float4 vv = h4_to_f4(__ldg(&hv[(size_t)s * 32 + lane]));
        a1.x += vv.x; a1.y += vv.y; a1.z += vv.z; a1.w += vv.w;
    }

    float4 a = {a0.x + a1.x, a0.y + a1.y, a0.z + a1.z, a0.w + a1.w};
    // acc layout: lane owns cols [4*lane, 4*lane+4) -> float4 index node*32+lane
    reinterpret_cast<float4*>(acc)[(size_t)node * 32 + lane] = a;
}

// ---------------------------------------------------------------------------
// launch
// ---------------------------------------------------------------------------
extern "C" void kernel_launch(void* const* d_in, const int* in_sizes, int n_in,
                              void* d_out, int out_size) {
    const float* x   = (const float*)d_in[0];
    const int*   ei  = (const int*)d_in[1];
    const float *W1 = (const float*)d_in[2],  *b1  = (const float*)d_in[3];
    const float *g1 = (const float*)d_in[4],  *be1 = (const float*)d_in[5];
    const float *m1 = (const float*)d_in[6],  *v1  = (const float*)d_in[7];
    const float *W2 = (const float*)d_in[8],  *b2  = (const float*)d_in[9];
    const float *g2 = (const float*)d_in[10], *be2 = (const float*)d_in[11];
    const float *m2 = (const float*)d_in[12], *v2  = (const float*)d_in[13];
    const float *Wc1 = (const float*)d_in[14], *bc1 = (const float*)d_in[15];
    const float *Wc2 = (const float*)d_in[16], *bc2 = (const float*)d_in[17];
    float* out = (float*)d_out;

    const int* src = ei;
    const int* dst = ei + EE;

    __half* hhb;
    float* ab;
    int *degb, *offb, *curb, *adjb;
    cudaGetSymbolAddress((void**)&hhb, g_hh);
    cudaGetSymbolAddress((void**)&ab, g_acc);
    cudaGetSymbolAddress((void**)&degb, g_deg);
    cudaGetSymbolAddress((void**)&offb, g_off);
    cudaGetSymbolAddress((void**)&curb, g_cur);
    cudaGetSymbolAddress((void**)&adjb, g_adj);

    const int GB = (NN + 63) / 64;
    const int AB = (NN * 32 + 255) / 256;

    const int SM128 = 64 * 128 * 4 + 64 * 128 * 8 + 1024;  // 99328
    const int SM64  = 64 * 128 * 4 + 64 * 64 * 8 + 1024;   // 66560

    cudaFuncSetAttribute(gemm_k<128, false, false, false>,
                         cudaFuncAttributeMaxDynamicSharedMemorySize, SM128);
    cudaFuncSetAttribute(gemm_k<128, false, true, false>,
                         cudaFuncAttributeMaxDynamicSharedMemorySize, SM128);
    cudaFuncSetAttribute(gemm_k<64, true, true, true>,
                         cudaFuncAttributeMaxDynamicSharedMemorySize, SM64);

    // CSR build
    zero_deg_k<<<(NN + 255) / 256, 256>>>(degb);
    deg_k<<<(EE + 255) / 256, 256>>>(dst, degb);
    scan_k<<<1, SCAN_T>>>(degb, offb, curb);
    fill_k<<<(EE + 255) / 256, 256>>>(src, dst, curb, adjb);

    // layer 1
    gemm_k<128, false, false, false><<<GB, 256, SM128>>>(x, W1, b1, hhb, nullptr,
        nullptr, nullptr, nullptr, nullptr, nullptr, nullptr, nullptr);
    agg_k<<<AB, 256>>>(adjb, offb, hhb, ab);

    // layer 2 (finalize of layer 1 fused into GEMM input)
    gemm_k<128, false, true, false><<<GB, 256, SM128>>>(ab, W2, b2, hhb, nullptr,
        offb, g1, be1, m1, v1, nullptr, nullptr);
    agg_k<<<AB, 256>>>(adjb, offb, hhb, ab);

    // classifier (finalize of layer 2 + Wc1 GEMM + Wc2 tail fused)
    gemm_k<64, true, true, true><<<GB, 256, SM64>>>(ab, Wc1, bc1, nullptr, out,
        offb, g2, be2, m2, v2, Wc2, bc2);
}